// round 13
// baseline (speedup 1.0000x reference)
#include <cuda_runtime.h>
#include <cuda_bf16.h>
#include <math.h>
#include <stdint.h>

// Problem constants
#define SEQ    2048
#define HID    2048
#define NH     32
#define NOPE   128
#define ROPE_D 64
#define QKD    192
#define VD     128
#define KV_RANK 512
#define SWIN   128
#define CKV_W  576
#define KV_W   8192
#define QW     6144
#define AOW    4096
#define NEGINF (-1000000000.0f)
#define ATTN_SCALE 0.07216878364870323f   // 192^-0.5
#define INV254 (1.0f/254.0f)
#define INV127 (1.0f/127.0f)

// ---------------- scratch (device globals; no allocation allowed) ----------------
__device__ float g_q[(size_t)SEQ * QW];
__device__ float g_ckv[(size_t)SEQ * CKV_W];
__device__ float g_kv[(size_t)SEQ * KV_W];
__device__ float g_krope[(size_t)SEQ * ROPE_D];
__device__ float g_attn[(size_t)SEQ * AOW];

// int8 two-limb buffers. Activations: [M, 2K] = limb1 | limb2 (K-major).
// Weights: TRANSPOSED [Npad, 2K] int8.
__device__ signed char g_aq[(size_t)SEQ * 2 * 4096];
__device__ signed char g_wqq[(size_t)QW * 2 * HID];
__device__ signed char g_wkvaq[(size_t)640 * 2 * HID];
__device__ signed char g_wkvbq[(size_t)KV_W * 2 * KV_RANK];
__device__ signed char g_woq[(size_t)HID * 2 * AOW];

// scales: activations per-row (float), weights per-col absmax as float-bits (int, for atomicMax)
__device__ float g_sa[SEQ];
__device__ int g_sbq[QW];
__device__ int g_sbkva[640];
__device__ int g_sbkvb[KV_W];
__device__ int g_sbo[HID];

// ---------------- scale init ----------------
__global__ void zero_scales()
{
    int i = blockIdx.x * blockDim.x + threadIdx.x;
    if (i < QW)   g_sbq[i] = 0;
    if (i < 640)  g_sbkva[i] = 0;
    if (i < KV_W) g_sbkvb[i] = 0;
    if (i < HID)  g_sbo[i] = 0;
}

// ---------------- per-column absmax of W[K,N] (k-split + atomicMax) ----------------
__global__ void colmax_w(const float* __restrict__ W, int* __restrict__ sbb,
                         int K, int N, int Npad, int kseg)
{
    int n = blockIdx.x * blockDim.x + threadIdx.x;
    if (n >= Npad) return;
    float m = 0.0f;
    if (n < N) {
        int k0 = blockIdx.y * kseg;
        #pragma unroll 4
        for (int k = k0; k < k0 + kseg; k++)
            m = fmaxf(m, fabsf(W[(size_t)k * N + n]));
    }
    atomicMax(&sbb[n], __float_as_int(m));   // floats >= 0: int order == float order
}

// ---------------- transpose + 2-limb quantize weights: W[K,N] -> Y[Npad, 2K] ----------------
__global__ __launch_bounds__(256) void quantT_w(const float* __restrict__ W,
                                                signed char* __restrict__ Y,
                                                const int* __restrict__ sbb,
                                                int K, int N)
{
    __shared__ float t[32][33];
    const int n0 = blockIdx.x * 32;
    const int k0 = blockIdx.y * 32;
    const int tx = threadIdx.x & 31;
    const int ty = threadIdx.x >> 5;
    #pragma unroll
    for (int i = 0; i < 4; i++) {
        int k = ty + i * 8;
        t[k][tx] = (n0 + tx < N) ? W[(size_t)(k0 + k) * N + n0 + tx] : 0.0f;
    }
    __syncthreads();
    #pragma unroll
    for (int i = 0; i < 4; i++) {
        int n = ty + i * 8;
        float maxv = fmaxf(__int_as_float(sbb[n0 + n]), 1e-30f);
        float inv = 127.0f / maxv;
        float x = t[tx][n];
        float q = x * inv;
        float l1 = rintf(q);
        float l2 = rintf((q - l1) * 254.0f);
        size_t rb = (size_t)(n0 + n) * 2 * K + k0 + tx;
        Y[rb]     = (signed char)(int)l1;
        Y[rb + K] = (signed char)(int)l2;
    }
}

// ---------------- per-row 2-limb quantize activations: X[M, ldx] (first K) -> Y[M, 2K] ----
__global__ __launch_bounds__(256) void quant_act(const float* __restrict__ X,
                                                 signed char* __restrict__ Y,
                                                 float* __restrict__ sa,
                                                 int ldx, int K)
{
    __shared__ float rmax[8];
    const int m = blockIdx.x;
    const int tid = threadIdx.x;
    const int lane = tid & 31;
    const int w = tid >> 5;
    const float* row = X + (size_t)m * ldx;

    float mx = 0.0f;
    for (int i = tid; i < K / 4; i += 256) {
        float4 v = *reinterpret_cast<const float4*>(&row[i * 4]);
        mx = fmaxf(mx, fmaxf(fmaxf(fabsf(v.x), fabsf(v.y)), fmaxf(fabsf(v.z), fabsf(v.w))));
    }
    #pragma unroll
    for (int o = 16; o > 0; o >>= 1) mx = fmaxf(mx, __shfl_xor_sync(0xFFFFFFFFu, mx, o));
    if (lane == 0) rmax[w] = mx;
    __syncthreads();
    float rowmax = 0.0f;
    #pragma unroll
    for (int i = 0; i < 8; i++) rowmax = fmaxf(rowmax, rmax[i]);
    float maxv = fmaxf(rowmax, 1e-30f);
    float inv = 127.0f / maxv;
    if (tid == 0) sa[m] = maxv * INV127;

    for (int i = tid; i < K / 4; i += 256) {
        float4 v = *reinterpret_cast<const float4*>(&row[i * 4]);
        float q[4] = {v.x * inv, v.y * inv, v.z * inv, v.w * inv};
        uint32_t p1 = 0, p2 = 0;
        #pragma unroll
        for (int j = 0; j < 4; j++) {
            int a1 = (int)rintf(q[j]);
            int a2 = (int)rintf((q[j] - (float)a1) * 254.0f);
            p1 |= ((uint32_t)a1 & 0xFFu) << (8 * j);
            p2 |= ((uint32_t)a2 & 0xFFu) << (8 * j);
        }
        *reinterpret_cast<uint32_t*>(&Y[(size_t)m * 2 * K + i * 4])     = p1;
        *reinterpret_cast<uint32_t*>(&Y[(size_t)m * 2 * K + K + i * 4]) = p2;
    }
}

// ---------------- mma / ldmatrix / cp.async wrappers ----------------
__device__ __forceinline__ void imma(int* c, const uint32_t* a, const uint32_t* b)
{
    asm volatile(
        "mma.sync.aligned.m16n8k32.row.col.s32.s8.s8.s32 "
        "{%0,%1,%2,%3}, {%4,%5,%6,%7}, {%8,%9}, {%0,%1,%2,%3};\n"
        : "+r"(c[0]), "+r"(c[1]), "+r"(c[2]), "+r"(c[3])
        : "r"(a[0]), "r"(a[1]), "r"(a[2]), "r"(a[3]),
          "r"(b[0]), "r"(b[1]));
}
__device__ __forceinline__ void ldsm4(uint32_t* r, uint32_t addr)
{
    asm volatile("ldmatrix.sync.aligned.m8n8.x4.shared.b16 {%0,%1,%2,%3}, [%4];"
                 : "=r"(r[0]), "=r"(r[1]), "=r"(r[2]), "=r"(r[3]) : "r"(addr));
}
__device__ __forceinline__ void cp16(uint32_t dst, const void* src)
{
    asm volatile("cp.async.cg.shared.global [%0], [%1], 16;"
                 :: "r"(dst), "l"(src));
}

// ---------------- int8 2-limb tensor GEMM ----------------
// C[2048, N] = sa[m]*sb[n]*( A1B1 + (A1B2 + A2B1)/254 ) + bias
// A: [M, 2K] int8; B: [Npad, 2K] int8 (transposed weights). Block 128x128, chunk=64 k,
// 256 thr, 8 warps (2m x 4n, warp 64x32), 3-stage cp.async, pad-80B rows (conflict-free ldsm).
#define RPAD   80                          // bytes per smem row (64 data + 16 pad)
#define TILE_Q (128 * RPAD)                // 10240 B
#define A1_OFF 0
#define A2_OFF TILE_Q
#define B1_OFF (2 * TILE_Q)
#define B2_OFF (3 * TILE_Q)
#define STG_Q  (4 * TILE_Q)                // 40960 B
#define NSTG   3
#define GEMM_SMEMQ (NSTG * STG_Q)          // 122880 B

__global__ __launch_bounds__(256) void gemm_s8(
    const signed char* __restrict__ A,
    const signed char* __restrict__ B,
    const float* __restrict__ sa,
    const int* __restrict__ sbb,
    const float* __restrict__ bias,
    float* __restrict__ C, int ldc,
    int N, int K)
{
    extern __shared__ signed char dsm[];

    const int tid  = threadIdx.x;
    const int lane = tid & 31;
    const int w    = tid >> 5;
    const int wm   = w >> 2;
    const int wn   = w & 3;
    const int bm   = blockIdx.y * 128;
    const int bn   = blockIdx.x * 128;
    const int lda2 = 2 * K;

    uint32_t sbase = (uint32_t)__cvta_generic_to_shared(dsm);

    int acc1[4][4][4], accm[4][4][4];
    #pragma unroll
    for (int mi = 0; mi < 4; mi++)
        #pragma unroll
        for (int ni = 0; ni < 4; ni++)
            #pragma unroll
            for (int e = 0; e < 4; e++) { acc1[mi][ni][e] = 0; accm[mi][ni][e] = 0; }

    const int nk = K / 64;

    auto issue = [&](int c) {
        if (c < nk) {
            int kk = c * 64;
            const signed char* A1 = A + kk;
            const signed char* A2 = A + K + kk;
            const signed char* B1 = B + kk;
            const signed char* B2 = B + K + kk;
            uint32_t st = sbase + (c % NSTG) * STG_Q;
            #pragma unroll
            for (int it = 0; it < 2; it++) {
                int lin = tid + it * 256;
                int r = lin >> 2, cc = lin & 3;
                uint32_t sm = r * RPAD + cc * 16;
                size_t aoff = (size_t)(bm + r) * lda2 + cc * 16;
                size_t boff = (size_t)(bn + r) * lda2 + cc * 16;
                cp16(st + A1_OFF + sm, A1 + aoff);
                cp16(st + A2_OFF + sm, A2 + aoff);
                cp16(st + B1_OFF + sm, B1 + boff);
                cp16(st + B2_OFF + sm, B2 + boff);
            }
        }
        asm volatile("cp.async.commit_group;");
    };

    issue(0);
    issue(1);

    for (int ch = 0; ch < nk; ch++) {
        uint32_t st = sbase + (ch % NSTG) * STG_Q;
        asm volatile("cp.async.wait_group %0;" :: "n"(NSTG - 2));
        __syncthreads();   // also orders prior-stage reads before overwrite

        issue(ch + 2);

        #pragma unroll
        for (int ks = 0; ks < 2; ks++) {
            // ---- B fragments (non-trans ldsm on [n][k] layout) ----
            uint32_t b1f[4][2], b2f[4][2];
            int koffB = ks * 32 + (((lane >> 3) & 1) << 4);
            #pragma unroll
            for (int bt = 0; bt < 2; bt++) {
                int nrow = wn * 32 + bt * 16 + ((lane >> 4) << 3) + (lane & 7);
                uint32_t r[4];
                ldsm4(r, st + B1_OFF + nrow * RPAD + koffB);
                b1f[bt * 2][0] = r[0]; b1f[bt * 2][1] = r[1];
                b1f[bt * 2 + 1][0] = r[2]; b1f[bt * 2 + 1][1] = r[3];
                ldsm4(r, st + B2_OFF + nrow * RPAD + koffB);
                b2f[bt * 2][0] = r[0]; b2f[bt * 2][1] = r[1];
                b2f[bt * 2 + 1][0] = r[2]; b2f[bt * 2 + 1][1] = r[3];
            }
            // ---- A1 fragments, passes 1+2 ----
            int rowA = wm * 64 + (lane & 15);
            int koffA = ks * 32 + ((lane >> 4) << 4);
            uint32_t a[4][4];
            #pragma unroll
            for (int mt = 0; mt < 4; mt++)
                ldsm4(a[mt], st + A1_OFF + (rowA + mt * 16) * RPAD + koffA);
            #pragma unroll
            for (int mt = 0; mt < 4; mt++)
                #pragma unroll
                for (int nt = 0; nt < 4; nt++) {
                    imma(acc1[mt][nt], a[mt], b1f[nt]);   // A1*B1
                    imma(accm[mt][nt], a[mt], b2f[nt]);   // A1*B2
                }
            // ---- A2 fragments, pass 3 ----
            uint32_t a2[4][4];
            #pragma unroll
            for (int mt = 0; mt < 4; mt++)
                ldsm4(a2[mt], st + A2_OFF + (rowA + mt * 16) * RPAD + koffA);
            #pragma unroll
            for (int mt = 0; mt < 4; mt++)
                #pragma unroll
                for (int nt = 0; nt < 4; nt++)
                    imma(accm[mt][nt], a2[mt], b1f[nt]);  // A2*B1
        }
    }

    // ---- epilogue ----
    const int g  = lane >> 2;
    const int q4 = (lane & 3) * 2;
    #pragma unroll
    for (int mi = 0; mi < 4; mi++) {
        int r0 = bm + wm * 64 + mi * 16 + g;
        float sa0 = sa[r0];
        float sa8 = sa[r0 + 8];
        #pragma unroll
        for (int ni = 0; ni < 4; ni++) {
            int c = bn + wn * 32 + ni * 8 + q4;
            if (c < N) {
                float sb0 = fmaxf(__int_as_float(sbb[c]), 1e-30f) * INV127;
                float sb1 = fmaxf(__int_as_float(sbb[c + 1]), 1e-30f) * INV127;
                float b0 = bias ? bias[c] : 0.0f;
                float b1 = bias ? bias[c + 1] : 0.0f;
                C[(size_t)r0 * ldc + c] =
                    sa0 * sb0 * ((float)acc1[mi][ni][0] + (float)accm[mi][ni][0] * INV254) + b0;
                C[(size_t)r0 * ldc + c + 1] =
                    sa0 * sb1 * ((float)acc1[mi][ni][1] + (float)accm[mi][ni][1] * INV254) + b1;
                C[(size_t)(r0 + 8) * ldc + c] =
                    sa8 * sb0 * ((float)acc1[mi][ni][2] + (float)accm[mi][ni][2] * INV254) + b0;
                C[(size_t)(r0 + 8) * ldc + c + 1] =
                    sa8 * sb1 * ((float)acc1[mi][ni][3] + (float)accm[mi][ni][3] * INV254) + b1;
            }
        }
    }
}

// ---------------- RoPE kernels ----------------
__global__ void rope_q_kernel(const float* __restrict__ cosp,
                              const float* __restrict__ sinp)
{
    int idx = blockIdx.x * blockDim.x + threadIdx.x;
    int r = idx & 31;
    int h = (idx >> 5) & 31;
    int i = idx >> 10;
    float* base = &g_q[(size_t)i * QW + h * QKD + NOPE];
    float x0 = base[r];
    float x1 = base[r + 32];
    float c0 = cosp[i * ROPE_D + r];
    float c1 = cosp[i * ROPE_D + 32 + r];
    float s0 = sinp[i * ROPE_D + r];
    float s1 = sinp[i * ROPE_D + 32 + r];
    base[r]      = x0 * c0 - x1 * s0;
    base[r + 32] = x1 * c1 + x0 * s1;
}

__global__ void rope_k_kernel(const float* __restrict__ cosp,
                              const float* __restrict__ sinp)
{
    int idx = blockIdx.x * blockDim.x + threadIdx.x;
    int r = idx & 31;
    int i = idx >> 5;
    const float* base = &g_ckv[(size_t)i * CKV_W + KV_RANK];
    float x0 = base[r];
    float x1 = base[r + 32];
    float c0 = cosp[i * ROPE_D + r];
    float c1 = cosp[i * ROPE_D + 32 + r];
    float s0 = sinp[i * ROPE_D + r];
    float s1 = sinp[i * ROPE_D + 32 + r];
    g_krope[(size_t)i * ROPE_D + r]      = x0 * c0 - x1 * s0;
    g_krope[(size_t)i * ROPE_D + 32 + r] = x1 * c1 + x0 * s1;
}

// ---------------- query-tiled sliding-window attention with sink ----------------
#define QT   16
#define QPAD 196
#define KPAD 196
#define VPAD 132
#define LW   144
__global__ __launch_bounds__(256) void attn_tile_kernel(const float* __restrict__ sinks)
{
    __shared__ float Qs[QT][QPAD];
    __shared__ float Ks[16][KPAD];
    __shared__ float Ls[QT][LW];
    __shared__ float Vs[16][VPAD];

    const int i0    = blockIdx.x * QT;
    const int h     = blockIdx.y;
    const int tid   = threadIdx.x;
    const int jbase = i0 - 127;

    #pragma unroll
    for (int it = 0; it < 3; it++) {
        int lin = tid + it * 256;
        int r   = lin / 48;
        int c4  = (lin % 48) * 4;
        float4 v = *reinterpret_cast<const float4*>(
            &g_q[(size_t)(i0 + r) * QW + h * QKD + c4]);
        *reinterpret_cast<float4*>(&Qs[r][c4]) = v;
    }
    __syncthreads();

    const int q = tid >> 4;
    const int j = tid & 15;

    for (int c = 0; c < 9; c++) {
        #pragma unroll
        for (int it = 0; it < 3; it++) {
            int lin = tid + it * 256;
            int r   = lin / 48;
            int c4  = (lin % 48) * 4;
            int key = jbase + c * 16 + r;
            float4 v = make_float4(0.f, 0.f, 0.f, 0.f);
            if (key >= 0 && key < SEQ) {
                if (c4 < NOPE)
                    v = *reinterpret_cast<const float4*>(
                        &g_kv[(size_t)key * KV_W + h * 256 + c4]);
                else
                    v = *reinterpret_cast<const float4*>(
                        &g_krope[(size_t)key * ROPE_D + (c4 - NOPE)]);
            }
            *reinterpret_cast<float4*>(&Ks[r][c4]) = v;
        }
        __syncthreads();
        float acc = 0.0f;
        #pragma unroll 8
        for (int d = 0; d < QKD; d++) acc = fmaf(Qs[q][d], Ks[j][d], acc);
        Ls[q][c * 16 + j] = acc;
        __syncthreads();
    }

    {
        const int lane = tid & 31;
        const int wrp  = tid >> 5;
        const float snk = sinks[h];
        #pragma unroll
        for (int rr = 0; rr < 2; rr++) {
            int row = wrp + rr * 8;
            float vals[5];
            float m = NEGINF;
            #pragma unroll
            for (int u = 0; u < 5; u++) {
                int t = lane + u * 32;
                float x = NEGINF;
                if (t < 143 && t >= row && t <= row + 127 && (jbase + t) >= 0)
                    x = Ls[row][t] * ATTN_SCALE;
                vals[u] = x;
                m = fmaxf(m, x);
            }
            #pragma unroll
            for (int o = 16; o > 0; o >>= 1) m = fmaxf(m, __shfl_xor_sync(0xFFFFFFFFu, m, o));
            m = fmaxf(m, snk);
            float s = 0.0f;
            #pragma unroll
            for (int u = 0; u < 5; u++) {
                float p = (vals[u] > 0.5f * NEGINF) ? __expf(vals[u] - m) : 0.0f;
                vals[u] = p;
                s += p;
            }
            #pragma unroll
            for (int o = 16; o > 0; o >>= 1) s += __shfl_xor_sync(0xFFFFFFFFu, s, o);
            float inv = 1.0f / (s + __expf(snk - m));
            #pragma unroll
            for (int u = 0; u < 5; u++) {
                int t = lane + u * 32;
                if (t < LW) Ls[row][t] = vals[u] * inv;
            }
        }
    }
    __syncthreads();

    const int dg = tid & 15;
    float oacc[8];
    #pragma unroll
    for (int e = 0; e < 8; e++) oacc[e] = 0.0f;

    for (int c = 0; c < 9; c++) {
        #pragma unroll
        for (int it = 0; it < 2; it++) {
            int lin = tid + it * 256;
            int r   = lin >> 5;
            int c4  = (lin & 31) * 4;
            int key = jbase + c * 16 + r;
            float4 v = make_float4(0.f, 0.f, 0.f, 0.f);
            if (key >= 0 && key < SEQ)
                v = *reinterpret_cast<const float4*>(
                    &g_kv[(size_t)key * KV_W + h * 256 + NOPE + c4]);
            *reinterpret_cast<float4*>(&Vs[r][c4]) = v;
        }
        __syncthreads();
        #pragma unroll
        for (int r = 0; r < 16; r++) {
            float p = Ls[q][c * 16 + r];
            float4 v0 = *reinterpret_cast<float4*>(&Vs[r][dg * 8]);
            float4 v1 = *reinterpret_cast<float4*>(&Vs[r][dg * 8 + 4]);
            oacc[0] = fmaf(p, v0.x, oacc[0]);
            oacc[1] = fmaf(p, v0.y, oacc[1]);
            oacc[2] = fmaf(p, v0.z, oacc[2]);
            oacc[3] = fmaf(p, v0.w, oacc[3]);
            oacc[4] = fmaf(p, v1.x, oacc[4]);
            oacc[5] = fmaf(p, v1.y, oacc[5]);
            oacc[6] = fmaf(p, v1.z, oacc[6]);
            oacc[7] = fmaf(p, v1.w, oacc[7]);
        }
        __syncthreads();
    }

    size_t obase = (size_t)(i0 + q) * AOW + h * VD + dg * 8;
    *reinterpret_cast<float4*>(&g_attn[obase])     = make_float4(oacc[0], oacc[1], oacc[2], oacc[3]);
    *reinterpret_cast<float4*>(&g_attn[obase + 4]) = make_float4(oacc[4], oacc[5], oacc[6], oacc[7]);
}

// ---------------- launch ----------------
extern "C" void kernel_launch(void* const* d_in, const int* in_sizes, int n_in,
                              void* d_out, int out_size)
{
    const float* hidden = (const float*)d_in[0];
    const float* cosp   = (const float*)d_in[1];
    const float* sinp   = (const float*)d_in[2];
    const float* Wq     = (const float*)d_in[3];
    const float* bq     = (const float*)d_in[4];
    const float* Wkva   = (const float*)d_in[5];
    const float* bkva   = (const float*)d_in[6];
    const float* Wkvb   = (const float*)d_in[7];
    const float* Wo     = (const float*)d_in[8];
    const float* bo     = (const float*)d_in[9];
    const float* sinks  = (const float*)d_in[10];
    float* out = (float*)d_out;

    float *q, *ckv, *kv, *attn, *sa;
    signed char *aq, *wqq, *wkvaq, *wkvbq, *woq;
    int *sbq, *sbkva, *sbkvb, *sbo;
    cudaGetSymbolAddress((void**)&q,     g_q);
    cudaGetSymbolAddress((void**)&ckv,   g_ckv);
    cudaGetSymbolAddress((void**)&kv,    g_kv);
    cudaGetSymbolAddress((void**)&attn,  g_attn);
    cudaGetSymbolAddress((void**)&sa,    g_sa);
    cudaGetSymbolAddress((void**)&aq,    g_aq);
    cudaGetSymbolAddress((void**)&wqq,   g_wqq);
    cudaGetSymbolAddress((void**)&wkvaq, g_wkvaq);
    cudaGetSymbolAddress((void**)&wkvbq, g_wkvbq);
    cudaGetSymbolAddress((void**)&woq,   g_woq);
    cudaGetSymbolAddress((void**)&sbq,   g_sbq);
    cudaGetSymbolAddress((void**)&sbkva, g_sbkva);
    cudaGetSymbolAddress((void**)&sbkvb, g_sbkvb);
    cudaGetSymbolAddress((void**)&sbo,   g_sbo);

    cudaFuncSetAttribute(gemm_s8,
                         cudaFuncAttributeMaxDynamicSharedMemorySize, GEMM_SMEMQ);

    // ---- scale init + weight quantization ----
    zero_scales<<<(KV_W + 255) / 256, 256>>>();
    colmax_w<<<dim3(QW / 256, 8), 256>>>(Wq, sbq, HID, QW, QW, HID / 8);
    colmax_w<<<dim3(3, 8), 256>>>(Wkva, sbkva, HID, CKV_W, 640, HID / 8);
    colmax_w<<<dim3(KV_W / 256, 8), 256>>>(Wkvb, sbkvb, KV_RANK, KV_W, KV_W, KV_RANK / 8);
    colmax_w<<<dim3(HID / 256, 8), 256>>>(Wo, sbo, AOW, HID, HID, AOW / 8);

    quantT_w<<<dim3(QW / 32, HID / 32), 256>>>(Wq, wqq, sbq, HID, QW);
    quantT_w<<<dim3(640 / 32, HID / 32), 256>>>(Wkva, wkvaq, sbkva, HID, CKV_W);
    quantT_w<<<dim3(KV_W / 32, KV_RANK / 32), 256>>>(Wkvb, wkvbq, sbkvb, KV_RANK, KV_W);
    quantT_w<<<dim3(HID / 32, AOW / 32), 256>>>(Wo, woq, sbo, AOW, HID);

    // ---- hidden quant, Q and KVA projections ----
    quant_act<<<SEQ, 256>>>(hidden, aq, sa, HID, HID);
    gemm_s8<<<dim3(QW / 128, SEQ / 128), 256, GEMM_SMEMQ>>>(
        aq, wqq, sa, sbq, bq, q, QW, QW, HID);
    gemm_s8<<<dim3(640 / 128, SEQ / 128), 256, GEMM_SMEMQ>>>(
        aq, wkvaq, sa, sbkva, bkva, ckv, CKV_W, CKV_W, HID);

    // ---- RoPE ----
    rope_q_kernel<<<(SEQ * NH * 32) / 256, 256>>>(cosp, sinp);
    rope_k_kernel<<<(SEQ * 32) / 256, 256>>>(cosp, sinp);

    // ---- latent quant, KV expansion ----
    quant_act<<<SEQ, 256>>>(ckv, aq, sa, CKV_W, KV_RANK);
    gemm_s8<<<dim3(KV_W / 128, SEQ / 128), 256, GEMM_SMEMQ>>>(
        aq, wkvbq, sa, sbkvb, nullptr, kv, KV_W, KV_W, KV_RANK);

    // ---- attention (query-tiled) ----
    attn_tile_kernel<<<dim3(SEQ / QT, NH), 256>>>(sinks);

    // ---- attn quant, output projection ----
    quant_act<<<SEQ, 256>>>(attn, aq, sa, AOW, AOW);
    gemm_s8<<<dim3(HID / 128, SEQ / 128), 256, GEMM_SMEMQ>>>(
        aq, woq, sa, sbo, bo, out, HID, HID, AOW);
}

// round 15
// speedup vs baseline: 2.2478x; 2.2478x over previous
#include <cuda_runtime.h>
#include <cuda_bf16.h>
#include <math.h>
#include <stdint.h>

// Problem constants
#define SEQ    2048
#define HID    2048
#define NH     32
#define NOPE   128
#define ROPE_D 64
#define QKD    192
#define VD     128
#define KV_RANK 512
#define SWIN   128
#define CKV_W  576
#define KV_W   8192
#define QW     6144
#define AOW    4096
#define NEGINF (-1000000000.0f)
#define ATTN_SCALE 0.07216878364870323f   // 192^-0.5

// ---------------- scratch (device globals; no allocation allowed) ----------------
__device__ float g_q[(size_t)SEQ * QW];
__device__ float g_ckv[(size_t)SEQ * CKV_W];
__device__ float g_kv[(size_t)SEQ * KV_W];
__device__ float g_krope[(size_t)SEQ * ROPE_D];
__device__ float g_attn[(size_t)SEQ * AOW];

// bf16 hi/lo split buffers
__device__ __nv_bfloat16 g_a2[(size_t)SEQ * 2 * 4096];
__device__ __nv_bfloat16 g_wq2[(size_t)2 * HID * QW];
__device__ __nv_bfloat16 g_wkva2[(size_t)2 * HID * CKV_W];
__device__ __nv_bfloat16 g_wkvb2[(size_t)2 * KV_RANK * KV_W];
__device__ __nv_bfloat16 g_wo2[(size_t)2 * AOW * HID];

// ---------------- helpers ----------------
__device__ __forceinline__ uint32_t pack2(__nv_bfloat16 a, __nv_bfloat16 b) {
    return (uint32_t)__bfloat16_as_ushort(a) | ((uint32_t)__bfloat16_as_ushort(b) << 16);
}
__device__ __forceinline__ void split1(float x, __nv_bfloat16& hi, __nv_bfloat16& lo) {
    hi = __float2bfloat16(x);
    lo = __float2bfloat16(x - __bfloat162float(hi));
}

__global__ void split_act(const float* __restrict__ X, __nv_bfloat16* __restrict__ Y,
                          int ldx, int K)
{
    int i = blockIdx.x * blockDim.x + threadIdx.x;
    int kq = K >> 2;
    int row = i / kq;
    int c4  = (i - row * kq) * 4;
    float4 v = *reinterpret_cast<const float4*>(&X[(size_t)row * ldx + c4]);
    __nv_bfloat16 h[4], l[4];
    split1(v.x, h[0], l[0]); split1(v.y, h[1], l[1]);
    split1(v.z, h[2], l[2]); split1(v.w, h[3], l[3]);
    uint2 ho, lo2;
    ho.x = pack2(h[0], h[1]); ho.y = pack2(h[2], h[3]);
    lo2.x = pack2(l[0], l[1]); lo2.y = pack2(l[2], l[3]);
    *reinterpret_cast<uint2*>(&Y[(size_t)row * 2 * K + c4])     = ho;
    *reinterpret_cast<uint2*>(&Y[(size_t)row * 2 * K + K + c4]) = lo2;
}

__global__ void split_wgt(const float* __restrict__ X, __nv_bfloat16* __restrict__ Y,
                          size_t total)
{
    size_t i = ((size_t)blockIdx.x * blockDim.x + threadIdx.x) * 4;
    float4 v = *reinterpret_cast<const float4*>(&X[i]);
    __nv_bfloat16 h[4], l[4];
    split1(v.x, h[0], l[0]); split1(v.y, h[1], l[1]);
    split1(v.z, h[2], l[2]); split1(v.w, h[3], l[3]);
    uint2 ho, lo2;
    ho.x = pack2(h[0], h[1]); ho.y = pack2(h[2], h[3]);
    lo2.x = pack2(l[0], l[1]); lo2.y = pack2(l[2], l[3]);
    *reinterpret_cast<uint2*>(&Y[i])         = ho;
    *reinterpret_cast<uint2*>(&Y[total + i]) = lo2;
}

// ---------------- mma / ldmatrix wrappers ----------------
__device__ __forceinline__ void mma16816(float* c, const uint32_t* a, const uint32_t* b)
{
    asm volatile(
        "mma.sync.aligned.m16n8k16.row.col.f32.bf16.bf16.f32 "
        "{%0,%1,%2,%3}, {%4,%5,%6,%7}, {%8,%9}, {%0,%1,%2,%3};\n"
        : "+f"(c[0]), "+f"(c[1]), "+f"(c[2]), "+f"(c[3])
        : "r"(a[0]), "r"(a[1]), "r"(a[2]), "r"(a[3]),
          "r"(b[0]), "r"(b[1]));
}
__device__ __forceinline__ void ldsm4(uint32_t* r, uint32_t addr)
{
    asm volatile("ldmatrix.sync.aligned.m8n8.x4.shared.b16 {%0,%1,%2,%3}, [%4];"
                 : "=r"(r[0]), "=r"(r[1]), "=r"(r[2]), "=r"(r[3]) : "r"(addr));
}
__device__ __forceinline__ void ldsm4t(uint32_t* r, uint32_t addr)
{
    asm volatile("ldmatrix.sync.aligned.m8n8.x4.trans.shared.b16 {%0,%1,%2,%3}, [%4];"
                 : "=r"(r[0]), "=r"(r[1]), "=r"(r[2]), "=r"(r[3]) : "r"(addr));
}
__device__ __forceinline__ void cp16(uint32_t dst, const void* src, int bytes)
{
    asm volatile("cp.async.cg.shared.global [%0], [%1], 16, %2;"
                 :: "r"(dst), "l"(src), "r"(bytes));
}

// ---------------- fused bf16x3 tensor GEMM ----------------
// C[2048, N] = Ah@Bh + Ah@Bl + Al@Bh (+bias), all staged per 32-k chunk.
// Block 128x128, BK=32, 256 thr, 8 warps (2m x 4n), 2-stage cp.async, 2 CTAs/SM.
#define APAD 40
#define AH_OFF 0
#define AL_OFF (128 * APAD)
#define BH_OFF (2 * 128 * APAD)
#define BL_OFF (2 * 128 * APAD + 32 * 128)
#define STG    (2 * 128 * APAD + 2 * 32 * 128)   // 18432 halves per stage
#define NSTAGES 2
#define GEMM_SMEM (NSTAGES * STG * 2)            // 73728 bytes

__global__ __launch_bounds__(256, 2) void gemm_split(
    const __nv_bfloat16* __restrict__ A2,
    const __nv_bfloat16* __restrict__ B2,
    const float* __restrict__ bias,
    float* __restrict__ C, int ldc,
    int N, int K)
{
    extern __shared__ __nv_bfloat16 dynsmem[];

    const int tid  = threadIdx.x;
    const int lane = tid & 31;
    const int w    = tid >> 5;
    const int wm   = w >> 2;
    const int wn   = w & 3;
    const int bm   = blockIdx.y * 128;
    const int bn   = blockIdx.x * 128;
    const int lda2 = 2 * K;

    uint32_t sbase = (uint32_t)__cvta_generic_to_shared(dynsmem);

    float acc[4][4][4];
    #pragma unroll
    for (int mi = 0; mi < 4; mi++)
        #pragma unroll
        for (int ni = 0; ni < 4; ni++)
            #pragma unroll
            for (int e = 0; e < 4; e++) acc[mi][ni][e] = 0.0f;

    const int nk = K / 32;

    auto issue = [&](int chunk, int stage) {
        if (chunk < nk) {
            int kk = chunk * 32;
            const __nv_bfloat16* Ah = A2 + kk;
            const __nv_bfloat16* Al = A2 + K + kk;
            const __nv_bfloat16* Bh = B2 + (size_t)kk * N;
            const __nv_bfloat16* Bl = B2 + (size_t)(K + kk) * N;
            uint32_t st = sbase + stage * STG * 2;
            #pragma unroll
            for (int it = 0; it < 2; it++) {
                int lin = tid + it * 256;
                int m = lin >> 2, c = lin & 3;
                size_t off = (size_t)(bm + m) * lda2 + c * 8;
                uint32_t sm = (m * APAD + c * 8) * 2;
                cp16(st + AH_OFF * 2 + sm, Ah + off, 16);
                cp16(st + AL_OFF * 2 + sm, Al + off, 16);
            }
            #pragma unroll
            for (int it = 0; it < 2; it++) {
                int lin = tid + it * 256;
                int k = lin >> 4, c = lin & 15;
                int col = bn + c * 8;
                int pred = (col + 8 <= N) ? 16 : 0;
                size_t off = (size_t)k * N + col;
                int phys = c ^ (k & 7);
                uint32_t sm = (k * 128 + phys * 8) * 2;
                cp16(st + BH_OFF * 2 + sm, Bh + off, pred);
                cp16(st + BL_OFF * 2 + sm, Bl + off, pred);
            }
        }
        asm volatile("cp.async.commit_group;");   // always commit (empty tail groups)
    };

    issue(0, 0);

    for (int ch = 0; ch < nk; ch++) {
        int st = ch & 1;
        asm volatile("cp.async.wait_group 0;");   // chunk ch landed
        __syncthreads();                          // visible to all; prior reads done

        issue(ch + 1, (ch + 1) & 1);              // load next while computing

        uint32_t stb = sbase + st * STG * 2;
        #pragma unroll
        for (int ks = 0; ks < 2; ks++) {
            int koff = ks * 16 + (lane >> 4) * 8;
            int krow = ks * 16 + (lane & 15);
            int arow = wm * 64 + (lane & 15);

            uint32_t bh[4][2], bl[4][2];
            #pragma unroll
            for (int bt = 0; bt < 2; bt++) {
                int cL = wn * 4 + bt * 2 + (lane >> 4);
                int phys = cL ^ (krow & 7);
                uint32_t r[4];
                ldsm4t(r, stb + BH_OFF * 2 + (krow * 128 + phys * 8) * 2);
                bh[bt * 2][0] = r[0]; bh[bt * 2][1] = r[1];
                bh[bt * 2 + 1][0] = r[2]; bh[bt * 2 + 1][1] = r[3];
                ldsm4t(r, stb + BL_OFF * 2 + (krow * 128 + phys * 8) * 2);
                bl[bt * 2][0] = r[0]; bl[bt * 2][1] = r[1];
                bl[bt * 2 + 1][0] = r[2]; bl[bt * 2 + 1][1] = r[3];
            }

            uint32_t af[4][4];
            #pragma unroll
            for (int mt = 0; mt < 4; mt++)
                ldsm4(af[mt], stb + AH_OFF * 2 + ((arow + mt * 16) * APAD + koff) * 2);
            #pragma unroll
            for (int mt = 0; mt < 4; mt++)
                #pragma unroll
                for (int nt = 0; nt < 4; nt++) {
                    mma16816(acc[mt][nt], af[mt], bh[nt]);   // hi*hi
                    mma16816(acc[mt][nt], af[mt], bl[nt]);   // hi*lo
                }
            #pragma unroll
            for (int mt = 0; mt < 4; mt++)
                ldsm4(af[mt], stb + AL_OFF * 2 + ((arow + mt * 16) * APAD + koff) * 2);
            #pragma unroll
            for (int mt = 0; mt < 4; mt++)
                #pragma unroll
                for (int nt = 0; nt < 4; nt++)
                    mma16816(acc[mt][nt], af[mt], bh[nt]);   // lo*hi
        }
    }

    // ---- store ----
    const int g  = lane >> 2;
    const int q4 = (lane & 3) * 2;
    #pragma unroll
    for (int mi = 0; mi < 4; mi++) {
        int r0 = bm + wm * 64 + mi * 16 + g;
        #pragma unroll
        for (int ni = 0; ni < 4; ni++) {
            int c = bn + wn * 32 + ni * 8 + q4;
            if (c < N) {
                float b0 = bias ? bias[c] : 0.0f;
                float b1 = bias ? bias[c + 1] : 0.0f;
                C[(size_t)r0 * ldc + c]           = acc[mi][ni][0] + b0;
                C[(size_t)r0 * ldc + c + 1]       = acc[mi][ni][1] + b1;
                C[(size_t)(r0 + 8) * ldc + c]     = acc[mi][ni][2] + b0;
                C[(size_t)(r0 + 8) * ldc + c + 1] = acc[mi][ni][3] + b1;
            }
        }
    }
}

// ---------------- RoPE kernels ----------------
__global__ void rope_q_kernel(const float* __restrict__ cosp,
                              const float* __restrict__ sinp)
{
    int idx = blockIdx.x * blockDim.x + threadIdx.x;
    int r = idx & 31;
    int h = (idx >> 5) & 31;
    int i = idx >> 10;
    float* base = &g_q[(size_t)i * QW + h * QKD + NOPE];
    float x0 = base[r];
    float x1 = base[r + 32];
    float c0 = cosp[i * ROPE_D + r];
    float c1 = cosp[i * ROPE_D + 32 + r];
    float s0 = sinp[i * ROPE_D + r];
    float s1 = sinp[i * ROPE_D + 32 + r];
    base[r]      = x0 * c0 - x1 * s0;
    base[r + 32] = x1 * c1 + x0 * s1;
}

__global__ void rope_k_kernel(const float* __restrict__ cosp,
                              const float* __restrict__ sinp)
{
    int idx = blockIdx.x * blockDim.x + threadIdx.x;
    int r = idx & 31;
    int i = idx >> 5;
    const float* base = &g_ckv[(size_t)i * CKV_W + KV_RANK];
    float x0 = base[r];
    float x1 = base[r + 32];
    float c0 = cosp[i * ROPE_D + r];
    float c1 = cosp[i * ROPE_D + 32 + r];
    float s0 = sinp[i * ROPE_D + r];
    float s1 = sinp[i * ROPE_D + 32 + r];
    g_krope[(size_t)i * ROPE_D + r]      = x0 * c0 - x1 * s0;
    g_krope[(size_t)i * ROPE_D + 32 + r] = x1 * c1 + x0 * s1;
}

// ---------------- query-tiled sliding-window attention with sink ----------------
#define QT   16
#define QPAD 196
#define KPAD 196
#define VPAD 132
#define LW   144
__global__ __launch_bounds__(256) void attn_tile_kernel(const float* __restrict__ sinks)
{
    __shared__ float Qs[QT][QPAD];
    __shared__ float Ks[16][KPAD];
    __shared__ float Ls[QT][LW];
    __shared__ float Vs[16][VPAD];

    const int i0    = blockIdx.x * QT;
    const int h     = blockIdx.y;
    const int tid   = threadIdx.x;
    const int jbase = i0 - 127;

    #pragma unroll
    for (int it = 0; it < 3; it++) {
        int lin = tid + it * 256;
        int r   = lin / 48;
        int c4  = (lin % 48) * 4;
        float4 v = *reinterpret_cast<const float4*>(
            &g_q[(size_t)(i0 + r) * QW + h * QKD + c4]);
        *reinterpret_cast<float4*>(&Qs[r][c4]) = v;
    }
    __syncthreads();

    const int q = tid >> 4;
    const int j = tid & 15;

    for (int c = 0; c < 9; c++) {
        #pragma unroll
        for (int it = 0; it < 3; it++) {
            int lin = tid + it * 256;
            int r   = lin / 48;
            int c4  = (lin % 48) * 4;
            int key = jbase + c * 16 + r;
            float4 v = make_float4(0.f, 0.f, 0.f, 0.f);
            if (key >= 0 && key < SEQ) {
                if (c4 < NOPE)
                    v = *reinterpret_cast<const float4*>(
                        &g_kv[(size_t)key * KV_W + h * 256 + c4]);
                else
                    v = *reinterpret_cast<const float4*>(
                        &g_krope[(size_t)key * ROPE_D + (c4 - NOPE)]);
            }
            *reinterpret_cast<float4*>(&Ks[r][c4]) = v;
        }
        __syncthreads();
        float acc = 0.0f;
        #pragma unroll
        for (int d = 0; d < QKD; d += 4) {
            float4 qv = *reinterpret_cast<const float4*>(&Qs[q][d]);
            float4 kv = *reinterpret_cast<const float4*>(&Ks[j][d]);
            acc = fmaf(qv.x, kv.x, acc);
            acc = fmaf(qv.y, kv.y, acc);
            acc = fmaf(qv.z, kv.z, acc);
            acc = fmaf(qv.w, kv.w, acc);
        }
        Ls[q][c * 16 + j] = acc;
        __syncthreads();
    }

    {
        const int lane = tid & 31;
        const int wrp  = tid >> 5;
        const float snk = sinks[h];
        #pragma unroll
        for (int rr = 0; rr < 2; rr++) {
            int row = wrp + rr * 8;
            float vals[5];
            float m = NEGINF;
            #pragma unroll
            for (int u = 0; u < 5; u++) {
                int t = lane + u * 32;
                float x = NEGINF;
                if (t < 143 && t >= row && t <= row + 127 && (jbase + t) >= 0)
                    x = Ls[row][t] * ATTN_SCALE;
                vals[u] = x;
                m = fmaxf(m, x);
            }
            #pragma unroll
            for (int o = 16; o > 0; o >>= 1) m = fmaxf(m, __shfl_xor_sync(0xFFFFFFFFu, m, o));
            m = fmaxf(m, snk);
            float s = 0.0f;
            #pragma unroll
            for (int u = 0; u < 5; u++) {
                float p = (vals[u] > 0.5f * NEGINF) ? __expf(vals[u] - m) : 0.0f;
                vals[u] = p;
                s += p;
            }
            #pragma unroll
            for (int o = 16; o > 0; o >>= 1) s += __shfl_xor_sync(0xFFFFFFFFu, s, o);
            float inv = 1.0f / (s + __expf(snk - m));
            #pragma unroll
            for (int u = 0; u < 5; u++) {
                int t = lane + u * 32;
                if (t < LW) Ls[row][t] = vals[u] * inv;
            }
        }
    }
    __syncthreads();

    const int dg = tid & 15;
    float oacc[8];
    #pragma unroll
    for (int e = 0; e < 8; e++) oacc[e] = 0.0f;

    for (int c = 0; c < 9; c++) {
        #pragma unroll
        for (int it = 0; it < 2; it++) {
            int lin = tid + it * 256;
            int r   = lin >> 5;
            int c4  = (lin & 31) * 4;
            int key = jbase + c * 16 + r;
            float4 v = make_float4(0.f, 0.f, 0.f, 0.f);
            if (key >= 0 && key < SEQ)
                v = *reinterpret_cast<const float4*>(
                    &g_kv[(size_t)key * KV_W + h * 256 + NOPE + c4]);
            *reinterpret_cast<float4*>(&Vs[r][c4]) = v;
        }
        __syncthreads();
        #pragma unroll
        for (int r = 0; r < 16; r++) {
            float p = Ls[q][c * 16 + r];
            float4 v0 = *reinterpret_cast<float4*>(&Vs[r][dg * 8]);
            float4 v1 = *reinterpret_cast<float4*>(&Vs[r][dg * 8 + 4]);
            oacc[0] = fmaf(p, v0.x, oacc[0]);
            oacc[1] = fmaf(p, v0.y, oacc[1]);
            oacc[2] = fmaf(p, v0.z, oacc[2]);
            oacc[3] = fmaf(p, v0.w, oacc[3]);
            oacc[4] = fmaf(p, v1.x, oacc[4]);
            oacc[5] = fmaf(p, v1.y, oacc[5]);
            oacc[6] = fmaf(p, v1.z, oacc[6]);
            oacc[7] = fmaf(p, v1.w, oacc[7]);
        }
        __syncthreads();
    }

    size_t obase = (size_t)(i0 + q) * AOW + h * VD + dg * 8;
    *reinterpret_cast<float4*>(&g_attn[obase])     = make_float4(oacc[0], oacc[1], oacc[2], oacc[3]);
    *reinterpret_cast<float4*>(&g_attn[obase + 4]) = make_float4(oacc[4], oacc[5], oacc[6], oacc[7]);
}

// ---------------- launch ----------------
extern "C" void kernel_launch(void* const* d_in, const int* in_sizes, int n_in,
                              void* d_out, int out_size)
{
    const float* hidden = (const float*)d_in[0];
    const float* cosp   = (const float*)d_in[1];
    const float* sinp   = (const float*)d_in[2];
    const float* Wq     = (const float*)d_in[3];
    const float* bq     = (const float*)d_in[4];
    const float* Wkva   = (const float*)d_in[5];
    const float* bkva   = (const float*)d_in[6];
    const float* Wkvb   = (const float*)d_in[7];
    const float* Wo     = (const float*)d_in[8];
    const float* bo     = (const float*)d_in[9];
    const float* sinks  = (const float*)d_in[10];
    float* out = (float*)d_out;

    float *q, *ckv, *kv, *attn;
    __nv_bfloat16 *a2, *wq2, *wkva2, *wkvb2, *wo2;
    cudaGetSymbolAddress((void**)&q,     g_q);
    cudaGetSymbolAddress((void**)&ckv,   g_ckv);
    cudaGetSymbolAddress((void**)&kv,    g_kv);
    cudaGetSymbolAddress((void**)&attn,  g_attn);
    cudaGetSymbolAddress((void**)&a2,    g_a2);
    cudaGetSymbolAddress((void**)&wq2,   g_wq2);
    cudaGetSymbolAddress((void**)&wkva2, g_wkva2);
    cudaGetSymbolAddress((void**)&wkvb2, g_wkvb2);
    cudaGetSymbolAddress((void**)&wo2,   g_wo2);

    cudaFuncSetAttribute(gemm_split,
                         cudaFuncAttributeMaxDynamicSharedMemorySize, GEMM_SMEM);

    // ---- weight splits ----
    split_wgt<<<(size_t)HID * QW / 4 / 256, 256>>>(Wq, wq2, (size_t)HID * QW);
    split_wgt<<<(size_t)HID * CKV_W / 4 / 256, 256>>>(Wkva, wkva2, (size_t)HID * CKV_W);
    split_wgt<<<(size_t)KV_RANK * KV_W / 4 / 256, 256>>>(Wkvb, wkvb2, (size_t)KV_RANK * KV_W);
    split_wgt<<<(size_t)AOW * HID / 4 / 256, 256>>>(Wo, wo2, (size_t)AOW * HID);

    // ---- hidden split, Q and KVA projections ----
    split_act<<<SEQ * HID / 4 / 256, 256>>>(hidden, a2, HID, HID);
    gemm_split<<<dim3(QW / 128, SEQ / 128), 256, GEMM_SMEM>>>(
        a2, wq2, bq, q, QW, QW, HID);
    gemm_split<<<dim3((CKV_W + 127) / 128, SEQ / 128), 256, GEMM_SMEM>>>(
        a2, wkva2, bkva, ckv, CKV_W, CKV_W, HID);

    // ---- RoPE ----
    rope_q_kernel<<<(SEQ * NH * 32) / 256, 256>>>(cosp, sinp);
    rope_k_kernel<<<(SEQ * 32) / 256, 256>>>(cosp, sinp);

    // ---- latent split, KV expansion ----
    split_act<<<SEQ * KV_RANK / 4 / 256, 256>>>(ckv, a2, CKV_W, KV_RANK);
    gemm_split<<<dim3(KV_W / 128, SEQ / 128), 256, GEMM_SMEM>>>(
        a2, wkvb2, nullptr, kv, KV_W, KV_W, KV_RANK);

    // ---- attention (query-tiled) ----
    attn_tile_kernel<<<dim3(SEQ / QT, NH), 256>>>(sinks);

    // ---- attn split, output projection ----
    split_act<<<SEQ * AOW / 4 / 256, 256>>>(attn, a2, AOW, AOW);
    gemm_split<<<dim3(HID / 128, SEQ / 128), 256, GEMM_SMEM>>>(
        a2, wo2, bo, out, HID, HID, AOW);
}

// round 16
// speedup vs baseline: 3.4533x; 1.5363x over previous
#include <cuda_runtime.h>
#include <cuda_fp16.h>
#include <math.h>
#include <stdint.h>

// Problem constants
#define SEQ    2048
#define HID    2048
#define NH     32
#define NOPE   128
#define ROPE_D 64
#define QKD    192
#define VD     128
#define KV_RANK 512
#define SWIN   128
#define CKV_W  576
#define KV_W   8192
#define QW     6144
#define AOW    4096
#define NEGINF (-1000000000.0f)
#define ATTN_SCALE 0.07216878364870323f   // 192^-0.5

// ---------------- scratch (device globals; no allocation allowed) ----------------
__device__ float g_q[(size_t)SEQ * QW];
__device__ float g_ckv[(size_t)SEQ * CKV_W];
__device__ float g_kv[(size_t)SEQ * KV_W];
__device__ float g_krope[(size_t)SEQ * ROPE_D];
__device__ float g_attn[(size_t)SEQ * AOW];

// fp16 buffers
__device__ __half g_ah[(size_t)SEQ * 4096];          // activations, max K=4096
__device__ __half g_wqh[(size_t)HID * QW];
__device__ __half g_wkvah[(size_t)HID * CKV_W];
__device__ __half g_wkvbh[(size_t)KV_RANK * KV_W];
__device__ __half g_woh[(size_t)AOW * HID];

// ---------------- converts ----------------
__global__ void cvt_act(const float* __restrict__ X, __half* __restrict__ Y,
                        int ldx, int K)
{
    int i = blockIdx.x * blockDim.x + threadIdx.x;
    int kq = K >> 2;
    int row = i / kq;
    int c4  = (i - row * kq) * 4;
    float4 v = *reinterpret_cast<const float4*>(&X[(size_t)row * ldx + c4]);
    __half h[4] = {__float2half_rn(v.x), __float2half_rn(v.y),
                   __float2half_rn(v.z), __float2half_rn(v.w)};
    *reinterpret_cast<uint2*>(&Y[(size_t)row * K + c4]) = *reinterpret_cast<uint2*>(h);
}

__global__ void cvt_wgt(const float* __restrict__ X, __half* __restrict__ Y)
{
    size_t i = ((size_t)blockIdx.x * blockDim.x + threadIdx.x) * 4;
    float4 v = *reinterpret_cast<const float4*>(&X[i]);
    __half h[4] = {__float2half_rn(v.x), __float2half_rn(v.y),
                   __float2half_rn(v.z), __float2half_rn(v.w)};
    *reinterpret_cast<uint2*>(&Y[i]) = *reinterpret_cast<uint2*>(h);
}

// ---------------- mma / ldmatrix wrappers ----------------
__device__ __forceinline__ void mma16816(float* c, const uint32_t* a, const uint32_t* b)
{
    asm volatile(
        "mma.sync.aligned.m16n8k16.row.col.f32.f16.f16.f32 "
        "{%0,%1,%2,%3}, {%4,%5,%6,%7}, {%8,%9}, {%0,%1,%2,%3};\n"
        : "+f"(c[0]), "+f"(c[1]), "+f"(c[2]), "+f"(c[3])
        : "r"(a[0]), "r"(a[1]), "r"(a[2]), "r"(a[3]),
          "r"(b[0]), "r"(b[1]));
}
__device__ __forceinline__ void ldsm4(uint32_t* r, uint32_t addr)
{
    asm volatile("ldmatrix.sync.aligned.m8n8.x4.shared.b16 {%0,%1,%2,%3}, [%4];"
                 : "=r"(r[0]), "=r"(r[1]), "=r"(r[2]), "=r"(r[3]) : "r"(addr));
}
__device__ __forceinline__ void ldsm4t(uint32_t* r, uint32_t addr)
{
    asm volatile("ldmatrix.sync.aligned.m8n8.x4.trans.shared.b16 {%0,%1,%2,%3}, [%4];"
                 : "=r"(r[0]), "=r"(r[1]), "=r"(r[2]), "=r"(r[3]) : "r"(addr));
}
__device__ __forceinline__ void cp16(uint32_t dst, const void* src, int bytes)
{
    asm volatile("cp.async.cg.shared.global [%0], [%1], 16, %2;"
                 :: "r"(dst), "l"(src), "r"(bytes));
}

// ---------------- fp16 single-pass tensor GEMM ----------------
// C[2048, N] = A@B (+bias).  A: [M,K] fp16; B: [K,N] fp16.
// Block 128x128, BK=32, 256 thr, 8 warps (2m x 4n), 3-stage cp.async, 2 CTAs/SM.
#define APAD 40
#define AH_OFF 0
#define BH_OFF (128 * APAD)                 // 5120 halves
#define STG    (128 * APAD + 32 * 128)      // 9216 halves per stage
#define NSTAGES 3
#define GEMM_SMEM (NSTAGES * STG * 2)       // 55296 bytes

__global__ __launch_bounds__(256, 2) void gemm_h(
    const __half* __restrict__ A,
    const __half* __restrict__ B,
    const float* __restrict__ bias,
    float* __restrict__ C, int ldc,
    int N, int K)
{
    extern __shared__ __half dynsmem[];

    const int tid  = threadIdx.x;
    const int lane = tid & 31;
    const int w    = tid >> 5;
    const int wm   = w >> 2;
    const int wn   = w & 3;
    const int bm   = blockIdx.y * 128;
    const int bn   = blockIdx.x * 128;

    uint32_t sbase = (uint32_t)__cvta_generic_to_shared(dynsmem);

    float acc[4][4][4];
    #pragma unroll
    for (int mi = 0; mi < 4; mi++)
        #pragma unroll
        for (int ni = 0; ni < 4; ni++)
            #pragma unroll
            for (int e = 0; e < 4; e++) acc[mi][ni][e] = 0.0f;

    const int nk = K / 32;

    auto issue = [&](int chunk) {
        if (chunk < nk) {
            int kk = chunk * 32;
            uint32_t st = sbase + (chunk % NSTAGES) * STG * 2;
            // A tile: 128 rows x 32 halves (4 x 16B chunks) = 512 cp16 -> 2/thread
            #pragma unroll
            for (int it = 0; it < 2; it++) {
                int lin = tid + it * 256;
                int m = lin >> 2, c = lin & 3;
                size_t off = (size_t)(bm + m) * K + kk + c * 8;
                cp16(st + AH_OFF * 2 + (m * APAD + c * 8) * 2, A + off, 16);
            }
            // B tile: 32 rows x 128 halves (16 x 16B chunks) = 512 cp16 -> 2/thread
            #pragma unroll
            for (int it = 0; it < 2; it++) {
                int lin = tid + it * 256;
                int k = lin >> 4, c = lin & 15;
                int col = bn + c * 8;
                int pred = (col + 8 <= N) ? 16 : 0;
                size_t off = (size_t)(kk + k) * N + col;
                int phys = c ^ (k & 7);
                cp16(st + BH_OFF * 2 + (k * 128 + phys * 8) * 2, B + off, pred);
            }
        }
        asm volatile("cp.async.commit_group;");   // always commit (empty tail groups)
    };

    issue(0);
    issue(1);

    for (int ch = 0; ch < nk; ch++) {
        uint32_t stb = sbase + (ch % NSTAGES) * STG * 2;
        asm volatile("cp.async.wait_group %0;" :: "n"(NSTAGES - 2));
        __syncthreads();   // chunk ch visible; prior-stage reads complete before overwrite

        issue(ch + 2);

        #pragma unroll
        for (int ks = 0; ks < 2; ks++) {
            int koff = ks * 16 + (lane >> 4) * 8;
            int krow = ks * 16 + (lane & 15);
            int arow = wm * 64 + (lane & 15);

            uint32_t bh[4][2];
            #pragma unroll
            for (int bt = 0; bt < 2; bt++) {
                int cL = wn * 4 + bt * 2 + (lane >> 4);
                int phys = cL ^ (krow & 7);
                uint32_t r[4];
                ldsm4t(r, stb + BH_OFF * 2 + (krow * 128 + phys * 8) * 2);
                bh[bt * 2][0] = r[0]; bh[bt * 2][1] = r[1];
                bh[bt * 2 + 1][0] = r[2]; bh[bt * 2 + 1][1] = r[3];
            }

            uint32_t af[4][4];
            #pragma unroll
            for (int mt = 0; mt < 4; mt++)
                ldsm4(af[mt], stb + AH_OFF * 2 + ((arow + mt * 16) * APAD + koff) * 2);
            #pragma unroll
            for (int mt = 0; mt < 4; mt++)
                #pragma unroll
                for (int nt = 0; nt < 4; nt++)
                    mma16816(acc[mt][nt], af[mt], bh[nt]);
        }
    }

    // ---- store ----
    const int g  = lane >> 2;
    const int q4 = (lane & 3) * 2;
    #pragma unroll
    for (int mi = 0; mi < 4; mi++) {
        int r0 = bm + wm * 64 + mi * 16 + g;
        #pragma unroll
        for (int ni = 0; ni < 4; ni++) {
            int c = bn + wn * 32 + ni * 8 + q4;
            if (c < N) {
                float b0 = bias ? bias[c] : 0.0f;
                float b1 = bias ? bias[c + 1] : 0.0f;
                C[(size_t)r0 * ldc + c]           = acc[mi][ni][0] + b0;
                C[(size_t)r0 * ldc + c + 1]       = acc[mi][ni][1] + b1;
                C[(size_t)(r0 + 8) * ldc + c]     = acc[mi][ni][2] + b0;
                C[(size_t)(r0 + 8) * ldc + c + 1] = acc[mi][ni][3] + b1;
            }
        }
    }
}

// ---------------- RoPE kernels ----------------
__global__ void rope_q_kernel(const float* __restrict__ cosp,
                              const float* __restrict__ sinp)
{
    int idx = blockIdx.x * blockDim.x + threadIdx.x;
    int r = idx & 31;
    int h = (idx >> 5) & 31;
    int i = idx >> 10;
    float* base = &g_q[(size_t)i * QW + h * QKD + NOPE];
    float x0 = base[r];
    float x1 = base[r + 32];
    float c0 = cosp[i * ROPE_D + r];
    float c1 = cosp[i * ROPE_D + 32 + r];
    float s0 = sinp[i * ROPE_D + r];
    float s1 = sinp[i * ROPE_D + 32 + r];
    base[r]      = x0 * c0 - x1 * s0;
    base[r + 32] = x1 * c1 + x0 * s1;
}

__global__ void rope_k_kernel(const float* __restrict__ cosp,
                              const float* __restrict__ sinp)
{
    int idx = blockIdx.x * blockDim.x + threadIdx.x;
    int r = idx & 31;
    int i = idx >> 5;
    const float* base = &g_ckv[(size_t)i * CKV_W + KV_RANK];
    float x0 = base[r];
    float x1 = base[r + 32];
    float c0 = cosp[i * ROPE_D + r];
    float c1 = cosp[i * ROPE_D + 32 + r];
    float s0 = sinp[i * ROPE_D + r];
    float s1 = sinp[i * ROPE_D + 32 + r];
    g_krope[(size_t)i * ROPE_D + r]      = x0 * c0 - x1 * s0;
    g_krope[(size_t)i * ROPE_D + 32 + r] = x1 * c1 + x0 * s1;
}

// ---------------- query-tiled sliding-window attention with sink ----------------
#define QT   16
#define QPAD 196
#define KPAD 196
#define VPAD 132
#define LW   144
__global__ __launch_bounds__(256) void attn_tile_kernel(const float* __restrict__ sinks)
{
    __shared__ float Qs[QT][QPAD];
    __shared__ float Ks[16][KPAD];
    __shared__ float Ls[QT][LW];
    __shared__ float Vs[16][VPAD];

    const int i0    = blockIdx.x * QT;
    const int h     = blockIdx.y;
    const int tid   = threadIdx.x;
    const int jbase = i0 - 127;

    #pragma unroll
    for (int it = 0; it < 3; it++) {
        int lin = tid + it * 256;
        int r   = lin / 48;
        int c4  = (lin % 48) * 4;
        float4 v = *reinterpret_cast<const float4*>(
            &g_q[(size_t)(i0 + r) * QW + h * QKD + c4]);
        *reinterpret_cast<float4*>(&Qs[r][c4]) = v;
    }
    __syncthreads();

    const int q = tid >> 4;
    const int j = tid & 15;

    for (int c = 0; c < 9; c++) {
        #pragma unroll
        for (int it = 0; it < 3; it++) {
            int lin = tid + it * 256;
            int r   = lin / 48;
            int c4  = (lin % 48) * 4;
            int key = jbase + c * 16 + r;
            float4 v = make_float4(0.f, 0.f, 0.f, 0.f);
            if (key >= 0 && key < SEQ) {
                if (c4 < NOPE)
                    v = *reinterpret_cast<const float4*>(
                        &g_kv[(size_t)key * KV_W + h * 256 + c4]);
                else
                    v = *reinterpret_cast<const float4*>(
                        &g_krope[(size_t)key * ROPE_D + (c4 - NOPE)]);
            }
            *reinterpret_cast<float4*>(&Ks[r][c4]) = v;
        }
        __syncthreads();
        float acc = 0.0f;
        #pragma unroll
        for (int d = 0; d < QKD; d += 4) {
            float4 qv = *reinterpret_cast<const float4*>(&Qs[q][d]);
            float4 kv = *reinterpret_cast<const float4*>(&Ks[j][d]);
            acc = fmaf(qv.x, kv.x, acc);
            acc = fmaf(qv.y, kv.y, acc);
            acc = fmaf(qv.z, kv.z, acc);
            acc = fmaf(qv.w, kv.w, acc);
        }
        Ls[q][c * 16 + j] = acc;
        __syncthreads();
    }

    {
        const int lane = tid & 31;
        const int wrp  = tid >> 5;
        const float snk = sinks[h];
        #pragma unroll
        for (int rr = 0; rr < 2; rr++) {
            int row = wrp + rr * 8;
            float vals[5];
            float m = NEGINF;
            #pragma unroll
            for (int u = 0; u < 5; u++) {
                int t = lane + u * 32;
                float x = NEGINF;
                if (t < 143 && t >= row && t <= row + 127 && (jbase + t) >= 0)
                    x = Ls[row][t] * ATTN_SCALE;
                vals[u] = x;
                m = fmaxf(m, x);
            }
            #pragma unroll
            for (int o = 16; o > 0; o >>= 1) m = fmaxf(m, __shfl_xor_sync(0xFFFFFFFFu, m, o));
            m = fmaxf(m, snk);
            float s = 0.0f;
            #pragma unroll
            for (int u = 0; u < 5; u++) {
                float p = (vals[u] > 0.5f * NEGINF) ? __expf(vals[u] - m) : 0.0f;
                vals[u] = p;
                s += p;
            }
            #pragma unroll
            for (int o = 16; o > 0; o >>= 1) s += __shfl_xor_sync(0xFFFFFFFFu, s, o);
            float inv = 1.0f / (s + __expf(snk - m));
            #pragma unroll
            for (int u = 0; u < 5; u++) {
                int t = lane + u * 32;
                if (t < LW) Ls[row][t] = vals[u] * inv;
            }
        }
    }
    __syncthreads();

    const int dg = tid & 15;
    float oacc[8];
    #pragma unroll
    for (int e = 0; e < 8; e++) oacc[e] = 0.0f;

    for (int c = 0; c < 9; c++) {
        #pragma unroll
        for (int it = 0; it < 2; it++) {
            int lin = tid + it * 256;
            int r   = lin >> 5;
            int c4  = (lin & 31) * 4;
            int key = jbase + c * 16 + r;
            float4 v = make_float4(0.f, 0.f, 0.f, 0.f);
            if (key >= 0 && key < SEQ)
                v = *reinterpret_cast<const float4*>(
                    &g_kv[(size_t)key * KV_W + h * 256 + NOPE + c4]);
            *reinterpret_cast<float4*>(&Vs[r][c4]) = v;
        }
        __syncthreads();
        #pragma unroll
        for (int r = 0; r < 16; r++) {
            float p = Ls[q][c * 16 + r];
            float4 v0 = *reinterpret_cast<float4*>(&Vs[r][dg * 8]);
            float4 v1 = *reinterpret_cast<float4*>(&Vs[r][dg * 8 + 4]);
            oacc[0] = fmaf(p, v0.x, oacc[0]);
            oacc[1] = fmaf(p, v0.y, oacc[1]);
            oacc[2] = fmaf(p, v0.z, oacc[2]);
            oacc[3] = fmaf(p, v0.w, oacc[3]);
            oacc[4] = fmaf(p, v1.x, oacc[4]);
            oacc[5] = fmaf(p, v1.y, oacc[5]);
            oacc[6] = fmaf(p, v1.z, oacc[6]);
            oacc[7] = fmaf(p, v1.w, oacc[7]);
        }
        __syncthreads();
    }

    size_t obase = (size_t)(i0 + q) * AOW + h * VD + dg * 8;
    *reinterpret_cast<float4*>(&g_attn[obase])     = make_float4(oacc[0], oacc[1], oacc[2], oacc[3]);
    *reinterpret_cast<float4*>(&g_attn[obase + 4]) = make_float4(oacc[4], oacc[5], oacc[6], oacc[7]);
}

// ---------------- launch ----------------
extern "C" void kernel_launch(void* const* d_in, const int* in_sizes, int n_in,
                              void* d_out, int out_size)
{
    const float* hidden = (const float*)d_in[0];
    const float* cosp   = (const float*)d_in[1];
    const float* sinp   = (const float*)d_in[2];
    const float* Wq     = (const float*)d_in[3];
    const float* bq     = (const float*)d_in[4];
    const float* Wkva   = (const float*)d_in[5];
    const float* bkva   = (const float*)d_in[6];
    const float* Wkvb   = (const float*)d_in[7];
    const float* Wo     = (const float*)d_in[8];
    const float* bo     = (const float*)d_in[9];
    const float* sinks  = (const float*)d_in[10];
    float* out = (float*)d_out;

    float *q, *ckv, *kv, *attn;
    __half *ah, *wqh, *wkvah, *wkvbh, *woh;
    cudaGetSymbolAddress((void**)&q,     g_q);
    cudaGetSymbolAddress((void**)&ckv,   g_ckv);
    cudaGetSymbolAddress((void**)&kv,    g_kv);
    cudaGetSymbolAddress((void**)&attn,  g_attn);
    cudaGetSymbolAddress((void**)&ah,    g_ah);
    cudaGetSymbolAddress((void**)&wqh,   g_wqh);
    cudaGetSymbolAddress((void**)&wkvah, g_wkvah);
    cudaGetSymbolAddress((void**)&wkvbh, g_wkvbh);
    cudaGetSymbolAddress((void**)&woh,   g_woh);

    cudaFuncSetAttribute(gemm_h,
                         cudaFuncAttributeMaxDynamicSharedMemorySize, GEMM_SMEM);

    // ---- weight converts ----
    cvt_wgt<<<(size_t)HID * QW / 4 / 256, 256>>>(Wq, wqh);
    cvt_wgt<<<(size_t)HID * CKV_W / 4 / 256, 256>>>(Wkva, wkvah);
    cvt_wgt<<<(size_t)KV_RANK * KV_W / 4 / 256, 256>>>(Wkvb, wkvbh);
    cvt_wgt<<<(size_t)AOW * HID / 4 / 256, 256>>>(Wo, woh);

    // ---- hidden convert, Q and KVA projections ----
    cvt_act<<<SEQ * HID / 4 / 256, 256>>>(hidden, ah, HID, HID);
    gemm_h<<<dim3(QW / 128, SEQ / 128), 256, GEMM_SMEM>>>(
        ah, wqh, bq, q, QW, QW, HID);
    gemm_h<<<dim3((CKV_W + 127) / 128, SEQ / 128), 256, GEMM_SMEM>>>(
        ah, wkvah, bkva, ckv, CKV_W, CKV_W, HID);

    // ---- RoPE ----
    rope_q_kernel<<<(SEQ * NH * 32) / 256, 256>>>(cosp, sinp);
    rope_k_kernel<<<(SEQ * 32) / 256, 256>>>(cosp, sinp);

    // ---- latent convert, KV expansion ----
    cvt_act<<<SEQ * KV_RANK / 4 / 256, 256>>>(ckv, ah, CKV_W, KV_RANK);
    gemm_h<<<dim3(KV_W / 128, SEQ / 128), 256, GEMM_SMEM>>>(
        ah, wkvbh, nullptr, kv, KV_W, KV_W, KV_RANK);

    // ---- attention (query-tiled) ----
    attn_tile_kernel<<<dim3(SEQ / QT, NH), 256>>>(sinks);

    // ---- attn convert, output projection ----
    cvt_act<<<SEQ * AOW / 4 / 256, 256>>>(attn, ah, AOW, AOW);
    gemm_h<<<dim3(HID / 128, SEQ / 128), 256, GEMM_SMEM>>>(
        ah, woh, bo, out, HID, HID, AOW);
}